// round 16
// baseline (speedup 1.0000x reference)
#include <cuda_runtime.h>
#include <cuda_bf16.h>
#include <cstdint>
#include <math.h>

#define B_      8
#define NTOK    1032
#define DIM     1024
#define HEADS   16
#define HD      64
#define SPECIAL 8
#define GRIDSZ  32
#define WIN     3
#define PADK    72          // bf16 elems per smem row (64 + 8 pad -> conflict-free)

// -------- scratch (device globals; no allocation allowed) --------
__device__ float g_qkv[B_ * NTOK * 3 * DIM];
__device__ float g_q[B_ * HEADS * NTOK * HD];
__device__ float g_k[B_ * HEADS * NTOK * HD];
__device__ float g_v[B_ * HEADS * NTOK * HD];
__device__ float g_attn[B_ * NTOK * DIM];

// ---------------- HMMA helper (sm_80+ PTX, no 'a' features) -----
__device__ __forceinline__ void mma16816(float* d, const uint32_t* a, const uint32_t* b) {
    asm volatile(
        "mma.sync.aligned.m16n8k16.row.col.f32.bf16.bf16.f32 "
        "{%0,%1,%2,%3}, {%4,%5,%6,%7}, {%8,%9}, {%0,%1,%2,%3};"
        : "+f"(d[0]), "+f"(d[1]), "+f"(d[2]), "+f"(d[3])
        : "r"(a[0]), "r"(a[1]), "r"(a[2]), "r"(a[3]), "r"(b[0]), "r"(b[1]));
}

// ================================================================
// HMMA GEMM (NT): C[M,N] = A[M,K] @ W[N,K]^T, fp32 in/out.
// bf16x3: C = Ah*Bh + Ah*Bl + Al*Bh   (fp32 accumulate).
// CTA tile 128x128, K-chunk 64, single smem buffer + LDG prefetch.
// 256 thr = 8 warps, warp tile 32(M) x 64(N).
// ================================================================
__global__ __launch_bounds__(256)
void gemm_hmma(const float* __restrict__ A, const float* __restrict__ W,
               float* __restrict__ C, int M, int N, int K)
{
    extern __shared__ __align__(16) __nv_bfloat16 sm[];
    __nv_bfloat16* AH = sm;                    // [128][PADK]
    __nv_bfloat16* AL = AH + 128 * PADK;
    __nv_bfloat16* BH = AL + 128 * PADK;
    __nv_bfloat16* BL = BH + 128 * PADK;

    const int tid  = threadIdx.x;
    const int m0   = blockIdx.y * 128;
    const int n0   = blockIdx.x * 128;
    const int lane = tid & 31;
    const int wid  = tid >> 5;
    const int wm   = (wid & 3) * 32;    // warp M offset
    const int wn   = (wid >> 2) * 64;   // warp N offset
    const int lr   = lane >> 2;         // 0..7
    const int lc   = lane & 3;          // 0..3

    float acc[16][4];
#pragma unroll
    for (int i = 0; i < 16; i++)
#pragma unroll
        for (int j = 0; j < 4; j++) acc[i][j] = 0.f;

    float4 va[8], vb[8];

    // ---- global prefetch of one K-chunk into registers ----
    auto ldg = [&](int k0) {
#pragma unroll
        for (int t = 0; t < 8; t++) {
            int g = tid + t * 256;           // 0..2047
            int r = g >> 4;                  // 0..127
            int c = (g & 15) << 2;           // 0..60
            int gm = m0 + r;
            va[t] = make_float4(0.f, 0.f, 0.f, 0.f);
            if (gm < M) va[t] = *(const float4*)(A + (size_t)gm * K + k0 + c);
            vb[t] = *(const float4*)(W + (size_t)(n0 + r) * K + k0 + c);
        }
    };
    // ---- registers -> bf16 hi/lo smem ----
    auto sts = [&]() {
#pragma unroll
        for (int t = 0; t < 8; t++) {
            int g = tid + t * 256;
            int r = g >> 4;
            int c = (g & 15) << 2;
            int o = r * PADK + c;
            float4 v = va[t];
            __nv_bfloat162 h01 = __floats2bfloat162_rn(v.x, v.y);
            __nv_bfloat162 h23 = __floats2bfloat162_rn(v.z, v.w);
            __nv_bfloat162 l01 = __floats2bfloat162_rn(v.x - __bfloat162float(h01.x),
                                                       v.y - __bfloat162float(h01.y));
            __nv_bfloat162 l23 = __floats2bfloat162_rn(v.z - __bfloat162float(h23.x),
                                                       v.w - __bfloat162float(h23.y));
            *(__nv_bfloat162*)(AH + o)     = h01;
            *(__nv_bfloat162*)(AH + o + 2) = h23;
            *(__nv_bfloat162*)(AL + o)     = l01;
            *(__nv_bfloat162*)(AL + o + 2) = l23;
            v = vb[t];
            h01 = __floats2bfloat162_rn(v.x, v.y);
            h23 = __floats2bfloat162_rn(v.z, v.w);
            l01 = __floats2bfloat162_rn(v.x - __bfloat162float(h01.x),
                                        v.y - __bfloat162float(h01.y));
            l23 = __floats2bfloat162_rn(v.z - __bfloat162float(h23.x),
                                        v.w - __bfloat162float(h23.y));
            *(__nv_bfloat162*)(BH + o)     = h01;
            *(__nv_bfloat162*)(BH + o + 2) = h23;
            *(__nv_bfloat162*)(BL + o)     = l01;
            *(__nv_bfloat162*)(BL + o + 2) = l23;
        }
    };

    const int NC = K >> 6;    // 64-wide K chunks
    ldg(0);
    sts();
    __syncthreads();

    for (int c = 0; c < NC; c++) {
        if (c + 1 < NC) ldg((c + 1) << 6);   // overlap LDG with compute

#pragma unroll
        for (int ks = 0; ks < 4; ks++) {
            const int kb = ks * 16;
            uint32_t ah[2][4], al[2][4], bh[8][2], bl[8][2];
#pragma unroll
            for (int mt = 0; mt < 2; mt++) {
                int o = (wm + mt * 16 + lr) * PADK + kb + lc * 2;
                ah[mt][0] = *(const uint32_t*)(AH + o);
                ah[mt][1] = *(const uint32_t*)(AH + o + 8 * PADK);
                ah[mt][2] = *(const uint32_t*)(AH + o + 8);
                ah[mt][3] = *(const uint32_t*)(AH + o + 8 * PADK + 8);
                al[mt][0] = *(const uint32_t*)(AL + o);
                al[mt][1] = *(const uint32_t*)(AL + o + 8 * PADK);
                al[mt][2] = *(const uint32_t*)(AL + o + 8);
                al[mt][3] = *(const uint32_t*)(AL + o + 8 * PADK + 8);
            }
#pragma unroll
            for (int nt = 0; nt < 8; nt++) {
                int o = (wn + nt * 8 + lr) * PADK + kb + lc * 2;
                bh[nt][0] = *(const uint32_t*)(BH + o);
                bh[nt][1] = *(const uint32_t*)(BH + o + 8);
                bl[nt][0] = *(const uint32_t*)(BL + o);
                bl[nt][1] = *(const uint32_t*)(BL + o + 8);
            }
#pragma unroll
            for (int mt = 0; mt < 2; mt++)
#pragma unroll
                for (int nt = 0; nt < 8; nt++) {
                    mma16816(acc[mt * 8 + nt], ah[mt], bh[nt]);
                    mma16816(acc[mt * 8 + nt], ah[mt], bl[nt]);
                    mma16816(acc[mt * 8 + nt], al[mt], bh[nt]);
                }
        }
        if (c + 1 < NC) {
            __syncthreads();   // all warps done reading this chunk
            sts();
            __syncthreads();   // new chunk visible
        }
    }

    // ---- epilogue: fragment -> fp32 C ----
#pragma unroll
    for (int mt = 0; mt < 2; mt++) {
#pragma unroll
        for (int nt = 0; nt < 8; nt++) {
            int row = m0 + wm + mt * 16 + lr;
            int col = n0 + wn + nt * 8 + lc * 2;
            float* f = acc[mt * 8 + nt];
            if (row < M)
                *(float2*)(C + (size_t)row * N + col) = make_float2(f[0], f[1]);
            if (row + 8 < M)
                *(float2*)(C + (size_t)(row + 8) * N + col) = make_float2(f[2], f[3]);
        }
    }
}

// ---------------------------------------------------------------
// Epilogue: per (b,n,h) warp. RMSNorm(q,k) + RoPE, copy v.
// ---------------------------------------------------------------
__global__ __launch_bounds__(256)
void qkv_epilogue(const float* __restrict__ qkv,
                  const float* __restrict__ fcos, const float* __restrict__ fsin,
                  const float* __restrict__ wq, const float* __restrict__ wk,
                  float* __restrict__ Qo, float* __restrict__ Ko, float* __restrict__ Vo)
{
    int gw   = (blockIdx.x * blockDim.x + threadIdx.x) >> 5;
    int lane = threadIdx.x & 31;
    if (gw >= B_ * NTOK * HEADS) return;
    int h  = gw % HEADS;
    int bn = gw / HEADS;
    int n  = bn % NTOK, b = bn / NTOK;

    const float* base = qkv + (size_t)bn * (3 * DIM) + h * HD;
    float q0 = base[lane],           q1 = base[lane + 32];
    float k0 = base[DIM + lane],     k1 = base[DIM + lane + 32];
    float v0 = base[2 * DIM + lane], v1 = base[2 * DIM + lane + 32];

    float ssq = q0 * q0 + q1 * q1;
    float ssk = k0 * k0 + k1 * k1;
#pragma unroll
    for (int o = 16; o; o >>= 1) {
        ssq += __shfl_xor_sync(0xffffffffu, ssq, o);
        ssk += __shfl_xor_sync(0xffffffffu, ssk, o);
    }
    float iq = rsqrtf(ssq * (1.f / HD) + 1e-6f);
    float ik = rsqrtf(ssk * (1.f / HD) + 1e-6f);
    q0 *= iq * wq[lane]; q1 *= iq * wq[lane + 32];
    k0 *= ik * wk[lane]; k1 *= ik * wk[lane + 32];

    float c0 = fcos[n * HD + lane], c1 = fcos[n * HD + lane + 32];
    float s0 = fsin[n * HD + lane], s1 = fsin[n * HD + lane + 32];
    float qa = q0 * c0 - q1 * s0, qb = q1 * c1 + q0 * s1;
    float ka = k0 * c0 - k1 * s0, kb = k1 * c1 + k0 * s1;

    size_t o = ((size_t)(b * HEADS + h) * NTOK + n) * HD;
    Qo[o + lane] = qa; Qo[o + lane + 32] = qb;
    Ko[o + lane] = ka; Ko[o + lane + 32] = kb;
    Vo[o + lane] = v0; Vo[o + lane + 32] = v1;
}

// ---------------------------------------------------------------
// Patch attention: CTA = (qr grid row, h, b).
// ---------------------------------------------------------------
__global__ __launch_bounds__(512)
void attn_patch(const float* __restrict__ Qg, const float* __restrict__ Kg,
                const float* __restrict__ Vg, float* __restrict__ O)
{
    extern __shared__ float smf[];
    float* Ks = smf;
    float* Vs = Ks + 240 * 68;
    float* Qs = Vs + 240 * 68;
    float* S  = Qs + 32 * 68;

    const int qr = blockIdx.x;
    const int h  = blockIdx.y;
    const int b  = blockIdx.z;
    const size_t bh = (size_t)(b * HEADS + h) * NTOK;
    const int kr0 = max(0, qr - WIN), kr1 = min(GRIDSZ - 1, qr + WIN);
    const int nk  = SPECIAL + (kr1 - kr0 + 1) * GRIDSZ;
    const int tid = threadIdx.x;

    for (int i = tid; i < nk * 16; i += 512) {
        int j = i >> 4, c = i & 15;
        int tok = (j < SPECIAL) ? j : (SPECIAL + kr0 * GRIDSZ + (j - SPECIAL));
        ((float4*)(Ks + j * 68))[c] = ((const float4*)(Kg + (bh + tok) * HD))[c];
        ((float4*)(Vs + j * 68))[c] = ((const float4*)(Vg + (bh + tok) * HD))[c];
    }
    for (int i = tid; i < 32 * 16; i += 512) {
        int j = i >> 4, c = i & 15;
        int tok = SPECIAL + qr * GRIDSZ + j;
        ((float4*)(Qs + j * 68))[c] = ((const float4*)(Qg + (bh + tok) * HD))[c];
    }
    __syncthreads();

    const int myq = tid >> 4;
    const int kl  = tid & 15;

    float4 qv[16];
#pragma unroll
    for (int c = 0; c < 16; c++) qv[c] = ((const float4*)(Qs + myq * 68))[c];

    float sreg[15];
#pragma unroll
    for (int i = 0; i < 15; i++) {
        int k = kl + i * 16;
        float s = -1e30f;
        if (k < nk) {
            bool ok = (k < SPECIAL) || (abs(((k - SPECIAL) & 31) - myq) <= WIN);
            if (ok) {
                float a = 0.f;
                const float4* kp = (const float4*)(Ks + k * 68);
#pragma unroll
                for (int c = 0; c < 16; c++) {
                    float4 kv = kp[c];
                    a += qv[c].x * kv.x + qv[c].y * kv.y + qv[c].z * kv.z + qv[c].w * kv.w;
                }
                s = a * 0.125f;
            }
        }
        sreg[i] = s;
    }
    float mx = -1e30f;
#pragma unroll
    for (int i = 0; i < 15; i++) mx = fmaxf(mx, sreg[i]);
#pragma unroll
    for (int o = 8; o; o >>= 1) mx = fmaxf(mx, __shfl_xor_sync(0xffffffffu, mx, o));
    float sum = 0.f;
#pragma unroll
    for (int i = 0; i < 15; i++) { sreg[i] = __expf(sreg[i] - mx); sum += sreg[i]; }
#pragma unroll
    for (int o = 8; o; o >>= 1) sum += __shfl_xor_sync(0xffffffffu, sum, o);
    float rinv = __frcp_rn(sum);
#pragma unroll
    for (int i = 0; i < 15; i++) {
        int k = kl + i * 16;
        if (k < nk) S[myq * 240 + k] = sreg[i] * rinv;
    }
    __syncthreads();

    float4 acc = make_float4(0.f, 0.f, 0.f, 0.f);
    for (int k = 0; k < nk; k++) {
        float p = S[myq * 240 + k];
        float4 v = ((const float4*)(Vs + k * 68))[kl];
        acc.x += p * v.x; acc.y += p * v.y; acc.z += p * v.z; acc.w += p * v.w;
    }
    int tok = SPECIAL + qr * GRIDSZ + myq;
    float* op = O + ((size_t)(b * NTOK + tok)) * DIM + h * HD + kl * 4;
    *(float4*)op = acc;
}

// ---------------------------------------------------------------
// Special queries: CTA per (q,h,b) = 1024 CTAs, 256 threads.
// ---------------------------------------------------------------
__global__ __launch_bounds__(256)
void attn_special(const float* __restrict__ Qg, const float* __restrict__ Kg,
                  const float* __restrict__ Vg, float* __restrict__ O)
{
    __shared__ __align__(16) float qs[HD];
    __shared__ float p[NTOK];
    __shared__ float red[8];
    __shared__ float pv[4][HD];

    const int q = blockIdx.x, h = blockIdx.y, b = blockIdx.z;
    const size_t bh = (size_t)(b * HEADS + h) * NTOK;
    const int tid = threadIdx.x, lane = tid & 31, w = tid >> 5;

    if (tid < HD) qs[tid] = Qg[(bh + q) * HD + tid];
    __syncthreads();

    float sc[5];
    float lmax = -1e30f;
#pragma unroll
    for (int i = 0; i < 5; i++) {
        int k = tid + i * 256;
        float s = -1e30f;
        if (k < NTOK) {
            const float4* kp = (const float4*)(Kg + (bh + k) * HD);
            float a = 0.f;
#pragma unroll
            for (int c = 0; c < 16; c++) {
                float4 kv = kp[c];
                float4 qv = ((const float4*)qs)[c];
                a += qv.x * kv.x + qv.y * kv.y + qv.z * kv.z + qv.w * kv.w;
            }
            s = a * 0.125f;
        }
        sc[i] = s;
        lmax = fmaxf(lmax, s);
    }
#pragma unroll
    for (int o = 16; o; o >>= 1) lmax = fmaxf(lmax, __shfl_xor_sync(0xffffffffu, lmax, o));
    if (lane == 0) red[w] = lmax;
    __syncthreads();
    float bmax = red[0];
#pragma unroll
    for (int i = 1; i < 8; i++) bmax = fmaxf(bmax, red[i]);
    __syncthreads();

    float lsum = 0.f;
#pragma unroll
    for (int i = 0; i < 5; i++) {
        int k = tid + i * 256;
        if (k < NTOK) { float e = __expf(sc[i] - bmax); p[k] = e; lsum += e; }
    }
#pragma unroll
    for (int o = 16; o; o >>= 1) lsum += __shfl_xor_sync(0xffffffffu, lsum, o);
    if (lane == 0) red[w] = lsum;
    __syncthreads();
    float bsum = red[0] + red[1] + red[2] + red[3] + red[4] + red[5] + red[6] + red[7];
    float rinv = __frcp_rn(bsum);

    int d = tid & 63, part = tid >> 6;
    float acc = 0.f;
    for (int k = part; k < NTOK; k += 4)
        acc += p[k] * Vg[(bh + k) * HD + d];
    pv[part][d] = acc;
    __syncthreads();
    if (tid < HD) {
        float r = (pv[0][tid] + pv[1][tid] + pv[2][tid] + pv[3][tid]) * rinv;
        O[((size_t)(b * NTOK + q)) * DIM + h * HD + tid] = r;
    }
}

// ---------------------------------------------------------------
extern "C" void kernel_launch(void* const* d_in, const int* in_sizes, int n_in,
                              void* d_out, int out_size)
{
    const float* hidden = (const float*)d_in[0];
    const float* fcos   = (const float*)d_in[1];
    const float* fsin   = (const float*)d_in[2];
    const float* qkv_w  = (const float*)d_in[3];
    const float* out_w  = (const float*)d_in[4];
    const float* wq     = (const float*)d_in[5];
    const float* wk     = (const float*)d_in[6];
    float* out = (float*)d_out;

    float *qkvb, *qb, *kb, *vb, *ab;
    cudaGetSymbolAddress((void**)&qkvb, g_qkv);
    cudaGetSymbolAddress((void**)&qb,   g_q);
    cudaGetSymbolAddress((void**)&kb,   g_k);
    cudaGetSymbolAddress((void**)&vb,   g_v);
    cudaGetSymbolAddress((void**)&ab,   g_attn);

    const int M = B_ * NTOK;                               // 8256
    const int GEMM_SMEM = 4 * 128 * PADK * 2;              // 73,728 B

    cudaFuncSetAttribute(gemm_hmma, cudaFuncAttributeMaxDynamicSharedMemorySize, GEMM_SMEM);

    // 1) QKV projection (HMMA bf16x3): [8256,1024] @ [3072,1024]^T
    dim3 g1(3 * DIM / 128, (M + 127) / 128);
    gemm_hmma<<<g1, 256, GEMM_SMEM>>>(hidden, qkv_w, qkvb, M, 3 * DIM, DIM);

    // 2) RMSNorm + RoPE epilogue -> Q,K,V [B,H,N,64]
    qkv_epilogue<<<(B_ * NTOK * HEADS) / 8, 256>>>(qkvb, fcos, fsin, wq, wk, qb, kb, vb);

    // 3) sparse window attention (patch queries)
    size_t smem = (size_t)(240 * 68 * 2 + 32 * 68 + 32 * 240) * sizeof(float);
    cudaFuncSetAttribute(attn_patch, cudaFuncAttributeMaxDynamicSharedMemorySize, (int)smem);
    attn_patch<<<dim3(GRIDSZ, HEADS, B_), 512, smem>>>(qb, kb, vb, ab);

    // 4) global attention for the 8 special queries
    attn_special<<<dim3(SPECIAL, HEADS, B_), 256>>>(qb, kb, vb, ab);

    // 5) output projection (HMMA bf16x3): [8256,1024] @ [1024,1024]^T
    dim3 g2(DIM / 128, (M + 127) / 128);
    gemm_hmma<<<g2, 256, GEMM_SMEM>>>(ab, out_w, out, M, DIM, DIM);
}

// round 17
// speedup vs baseline: 1.0038x; 1.0038x over previous
#include <cuda_runtime.h>
#include <cuda_bf16.h>
#include <cstdint>
#include <math.h>

#define B_      8
#define NTOK    1032
#define DIM     1024
#define HEADS   16
#define HD      64
#define SPECIAL 8
#define GRIDSZ  32
#define WIN     3
#define PADK    72          // bf16 elems per smem row (64 + 8 pad -> conflict-free)

// -------- scratch (device globals; no allocation allowed) --------
__device__ float g_qkv[B_ * NTOK * 3 * DIM];
__device__ float g_q[B_ * HEADS * NTOK * HD];
__device__ float g_k[B_ * HEADS * NTOK * HD];
__device__ float g_v[B_ * HEADS * NTOK * HD];
__device__ float g_attn[B_ * NTOK * DIM];

// ---------------- HMMA helper (sm_80+ PTX, no 'a' features) -----
__device__ __forceinline__ void mma16816(float* d, const uint32_t* a, const uint32_t* b) {
    asm volatile(
        "mma.sync.aligned.m16n8k16.row.col.f32.bf16.bf16.f32 "
        "{%0,%1,%2,%3}, {%4,%5,%6,%7}, {%8,%9}, {%0,%1,%2,%3};"
        : "+f"(d[0]), "+f"(d[1]), "+f"(d[2]), "+f"(d[3])
        : "r"(a[0]), "r"(a[1]), "r"(a[2]), "r"(a[3]), "r"(b[0]), "r"(b[1]));
}

// ================================================================
// HMMA GEMM (NT): C[M,N] = A[M,K] @ W[N,K]^T, fp32 in/out.
// bf16x3: C = Ah*Bh + Ah*Bl + Al*Bh   (fp32 accumulate).
// CTA tile 128x128, K-chunk 64, single smem buffer + LDG prefetch.
// 256 thr = 8 warps, warp tile 32(M) x 64(N).
// ================================================================
__global__ __launch_bounds__(256)
void gemm_hmma(const float* __restrict__ A, const float* __restrict__ W,
               float* __restrict__ C, int M, int N, int K)
{
    extern __shared__ __align__(16) __nv_bfloat16 sm[];
    __nv_bfloat16* AH = sm;                    // [128][PADK]
    __nv_bfloat16* AL = AH + 128 * PADK;
    __nv_bfloat16* BH = AL + 128 * PADK;
    __nv_bfloat16* BL = BH + 128 * PADK;

    const int tid  = threadIdx.x;
    const int m0   = blockIdx.y * 128;
    const int n0   = blockIdx.x * 128;
    const int lane = tid & 31;
    const int wid  = tid >> 5;
    const int wm   = (wid & 3) * 32;    // warp M offset
    const int wn   = (wid >> 2) * 64;   // warp N offset
    const int lr   = lane >> 2;         // 0..7
    const int lc   = lane & 3;          // 0..3

    float acc[16][4];
#pragma unroll
    for (int i = 0; i < 16; i++)
#pragma unroll
        for (int j = 0; j < 4; j++) acc[i][j] = 0.f;

    float4 va[8], vb[8];

    // ---- global prefetch of one K-chunk into registers ----
    auto ldg = [&](int k0) {
#pragma unroll
        for (int t = 0; t < 8; t++) {
            int g = tid + t * 256;           // 0..2047
            int r = g >> 4;                  // 0..127
            int c = (g & 15) << 2;           // 0..60
            int gm = m0 + r;
            va[t] = make_float4(0.f, 0.f, 0.f, 0.f);
            if (gm < M) va[t] = *(const float4*)(A + (size_t)gm * K + k0 + c);
            vb[t] = *(const float4*)(W + (size_t)(n0 + r) * K + k0 + c);
        }
    };
    // ---- registers -> bf16 hi/lo smem ----
    auto sts = [&]() {
#pragma unroll
        for (int t = 0; t < 8; t++) {
            int g = tid + t * 256;
            int r = g >> 4;
            int c = (g & 15) << 2;
            int o = r * PADK + c;
            float4 v = va[t];
            __nv_bfloat162 h01 = __floats2bfloat162_rn(v.x, v.y);
            __nv_bfloat162 h23 = __floats2bfloat162_rn(v.z, v.w);
            __nv_bfloat162 l01 = __floats2bfloat162_rn(v.x - __bfloat162float(h01.x),
                                                       v.y - __bfloat162float(h01.y));
            __nv_bfloat162 l23 = __floats2bfloat162_rn(v.z - __bfloat162float(h23.x),
                                                       v.w - __bfloat162float(h23.y));
            *(__nv_bfloat162*)(AH + o)     = h01;
            *(__nv_bfloat162*)(AH + o + 2) = h23;
            *(__nv_bfloat162*)(AL + o)     = l01;
            *(__nv_bfloat162*)(AL + o + 2) = l23;
            v = vb[t];
            h01 = __floats2bfloat162_rn(v.x, v.y);
            h23 = __floats2bfloat162_rn(v.z, v.w);
            l01 = __floats2bfloat162_rn(v.x - __bfloat162float(h01.x),
                                        v.y - __bfloat162float(h01.y));
            l23 = __floats2bfloat162_rn(v.z - __bfloat162float(h23.x),
                                        v.w - __bfloat162float(h23.y));
            *(__nv_bfloat162*)(BH + o)     = h01;
            *(__nv_bfloat162*)(BH + o + 2) = h23;
            *(__nv_bfloat162*)(BL + o)     = l01;
            *(__nv_bfloat162*)(BL + o + 2) = l23;
        }
    };

    const int NC = K >> 6;    // 64-wide K chunks
    ldg(0);
    sts();
    __syncthreads();

    for (int c = 0; c < NC; c++) {
        if (c + 1 < NC) ldg((c + 1) << 6);   // overlap LDG with compute

#pragma unroll
        for (int ks = 0; ks < 4; ks++) {
            const int kb = ks * 16;
            uint32_t ah[2][4], al[2][4], bh[8][2], bl[8][2];
#pragma unroll
            for (int mt = 0; mt < 2; mt++) {
                int o = (wm + mt * 16 + lr) * PADK + kb + lc * 2;
                ah[mt][0] = *(const uint32_t*)(AH + o);
                ah[mt][1] = *(const uint32_t*)(AH + o + 8 * PADK);
                ah[mt][2] = *(const uint32_t*)(AH + o + 8);
                ah[mt][3] = *(const uint32_t*)(AH + o + 8 * PADK + 8);
                al[mt][0] = *(const uint32_t*)(AL + o);
                al[mt][1] = *(const uint32_t*)(AL + o + 8 * PADK);
                al[mt][2] = *(const uint32_t*)(AL + o + 8);
                al[mt][3] = *(const uint32_t*)(AL + o + 8 * PADK + 8);
            }
#pragma unroll
            for (int nt = 0; nt < 8; nt++) {
                int o = (wn + nt * 8 + lr) * PADK + kb + lc * 2;
                bh[nt][0] = *(const uint32_t*)(BH + o);
                bh[nt][1] = *(const uint32_t*)(BH + o + 8);
                bl[nt][0] = *(const uint32_t*)(BL + o);
                bl[nt][1] = *(const uint32_t*)(BL + o + 8);
            }
#pragma unroll
            for (int mt = 0; mt < 2; mt++)
#pragma unroll
                for (int nt = 0; nt < 8; nt++) {
                    mma16816(acc[mt * 8 + nt], ah[mt], bh[nt]);
                    mma16816(acc[mt * 8 + nt], ah[mt], bl[nt]);
                    mma16816(acc[mt * 8 + nt], al[mt], bh[nt]);
                }
        }
        if (c + 1 < NC) {
            __syncthreads();   // all warps done reading this chunk
            sts();
            __syncthreads();   // new chunk visible
        }
    }

    // ---- epilogue: fragment -> fp32 C ----
#pragma unroll
    for (int mt = 0; mt < 2; mt++) {
#pragma unroll
        for (int nt = 0; nt < 8; nt++) {
            int row = m0 + wm + mt * 16 + lr;
            int col = n0 + wn + nt * 8 + lc * 2;
            float* f = acc[mt * 8 + nt];
            if (row < M)
                *(float2*)(C + (size_t)row * N + col) = make_float2(f[0], f[1]);
            if (row + 8 < M)
                *(float2*)(C + (size_t)(row + 8) * N + col) = make_float2(f[2], f[3]);
        }
    }
}

// ---------------------------------------------------------------
// Epilogue: per (b,n,h) warp. RMSNorm(q,k) + RoPE, copy v.
// ---------------------------------------------------------------
__global__ __launch_bounds__(256)
void qkv_epilogue(const float* __restrict__ qkv,
                  const float* __restrict__ fcos, const float* __restrict__ fsin,
                  const float* __restrict__ wq, const float* __restrict__ wk,
                  float* __restrict__ Qo, float* __restrict__ Ko, float* __restrict__ Vo)
{
    int gw   = (blockIdx.x * blockDim.x + threadIdx.x) >> 5;
    int lane = threadIdx.x & 31;
    if (gw >= B_ * NTOK * HEADS) return;
    int h  = gw % HEADS;
    int bn = gw / HEADS;
    int n  = bn % NTOK, b = bn / NTOK;

    const float* base = qkv + (size_t)bn * (3 * DIM) + h * HD;
    float q0 = base[lane],           q1 = base[lane + 32];
    float k0 = base[DIM + lane],     k1 = base[DIM + lane + 32];
    float v0 = base[2 * DIM + lane], v1 = base[2 * DIM + lane + 32];

    float ssq = q0 * q0 + q1 * q1;
    float ssk = k0 * k0 + k1 * k1;
#pragma unroll
    for (int o = 16; o; o >>= 1) {
        ssq += __shfl_xor_sync(0xffffffffu, ssq, o);
        ssk += __shfl_xor_sync(0xffffffffu, ssk, o);
    }
    float iq = rsqrtf(ssq * (1.f / HD) + 1e-6f);
    float ik = rsqrtf(ssk * (1.f / HD) + 1e-6f);
    q0 *= iq * wq[lane]; q1 *= iq * wq[lane + 32];
    k0 *= ik * wk[lane]; k1 *= ik * wk[lane + 32];

    float c0 = fcos[n * HD + lane], c1 = fcos[n * HD + lane + 32];
    float s0 = fsin[n * HD + lane], s1 = fsin[n * HD + lane + 32];
    float qa = q0 * c0 - q1 * s0, qb = q1 * c1 + q0 * s1;
    float ka = k0 * c0 - k1 * s0, kb = k1 * c1 + k0 * s1;

    size_t o = ((size_t)(b * HEADS + h) * NTOK + n) * HD;
    Qo[o + lane] = qa; Qo[o + lane + 32] = qb;
    Ko[o + lane] = ka; Ko[o + lane + 32] = kb;
    Vo[o + lane] = v0; Vo[o + lane + 32] = v1;
}

// ---------------------------------------------------------------
// Patch attention: CTA = (qr grid row, h, b).
// ---------------------------------------------------------------
__global__ __launch_bounds__(512)
void attn_patch(const float* __restrict__ Qg, const float* __restrict__ Kg,
                const float* __restrict__ Vg, float* __restrict__ O)
{
    extern __shared__ float smf[];
    float* Ks = smf;
    float* Vs = Ks + 240 * 68;
    float* Qs = Vs + 240 * 68;
    float* S  = Qs + 32 * 68;

    const int qr = blockIdx.x;
    const int h  = blockIdx.y;
    const int b  = blockIdx.z;
    const size_t bh = (size_t)(b * HEADS + h) * NTOK;
    const int kr0 = max(0, qr - WIN), kr1 = min(GRIDSZ - 1, qr + WIN);
    const int nk  = SPECIAL + (kr1 - kr0 + 1) * GRIDSZ;
    const int tid = threadIdx.x;

    for (int i = tid; i < nk * 16; i += 512) {
        int j = i >> 4, c = i & 15;
        int tok = (j < SPECIAL) ? j : (SPECIAL + kr0 * GRIDSZ + (j - SPECIAL));
        ((float4*)(Ks + j * 68))[c] = ((const float4*)(Kg + (bh + tok) * HD))[c];
        ((float4*)(Vs + j * 68))[c] = ((const float4*)(Vg + (bh + tok) * HD))[c];
    }
    for (int i = tid; i < 32 * 16; i += 512) {
        int j = i >> 4, c = i & 15;
        int tok = SPECIAL + qr * GRIDSZ + j;
        ((float4*)(Qs + j * 68))[c] = ((const float4*)(Qg + (bh + tok) * HD))[c];
    }
    __syncthreads();

    const int myq = tid >> 4;
    const int kl  = tid & 15;

    float4 qv[16];
#pragma unroll
    for (int c = 0; c < 16; c++) qv[c] = ((const float4*)(Qs + myq * 68))[c];

    float sreg[15];
#pragma unroll
    for (int i = 0; i < 15; i++) {
        int k = kl + i * 16;
        float s = -1e30f;
        if (k < nk) {
            bool ok = (k < SPECIAL) || (abs(((k - SPECIAL) & 31) - myq) <= WIN);
            if (ok) {
                float a = 0.f;
                const float4* kp = (const float4*)(Ks + k * 68);
#pragma unroll
                for (int c = 0; c < 16; c++) {
                    float4 kv = kp[c];
                    a += qv[c].x * kv.x + qv[c].y * kv.y + qv[c].z * kv.z + qv[c].w * kv.w;
                }
                s = a * 0.125f;
            }
        }
        sreg[i] = s;
    }
    float mx = -1e30f;
#pragma unroll
    for (int i = 0; i < 15; i++) mx = fmaxf(mx, sreg[i]);
#pragma unroll
    for (int o = 8; o; o >>= 1) mx = fmaxf(mx, __shfl_xor_sync(0xffffffffu, mx, o));
    float sum = 0.f;
#pragma unroll
    for (int i = 0; i < 15; i++) { sreg[i] = __expf(sreg[i] - mx); sum += sreg[i]; }
#pragma unroll
    for (int o = 8; o; o >>= 1) sum += __shfl_xor_sync(0xffffffffu, sum, o);
    float rinv = __frcp_rn(sum);
#pragma unroll
    for (int i = 0; i < 15; i++) {
        int k = kl + i * 16;
        if (k < nk) S[myq * 240 + k] = sreg[i] * rinv;
    }
    __syncthreads();

    float4 acc = make_float4(0.f, 0.f, 0.f, 0.f);
    for (int k = 0; k < nk; k++) {
        float p = S[myq * 240 + k];
        float4 v = ((const float4*)(Vs + k * 68))[kl];
        acc.x += p * v.x; acc.y += p * v.y; acc.z += p * v.z; acc.w += p * v.w;
    }
    int tok = SPECIAL + qr * GRIDSZ + myq;
    float* op = O + ((size_t)(b * NTOK + tok)) * DIM + h * HD + kl * 4;
    *(float4*)op = acc;
}

// ---------------------------------------------------------------
// Special queries: CTA per (q,h,b) = 1024 CTAs, 256 threads.
// ---------------------------------------------------------------
__global__ __launch_bounds__(256)
void attn_special(const float* __restrict__ Qg, const float* __restrict__ Kg,
                  const float* __restrict__ Vg, float* __restrict__ O)
{
    __shared__ __align__(16) float qs[HD];
    __shared__ float p[NTOK];
    __shared__ float red[8];
    __shared__ float pv[4][HD];

    const int q = blockIdx.x, h = blockIdx.y, b = blockIdx.z;
    const size_t bh = (size_t)(b * HEADS + h) * NTOK;
    const int tid = threadIdx.x, lane = tid & 31, w = tid >> 5;

    if (tid < HD) qs[tid] = Qg[(bh + q) * HD + tid];
    __syncthreads();

    float sc[5];
    float lmax = -1e30f;
#pragma unroll
    for (int i = 0; i < 5; i++) {
        int k = tid + i * 256;
        float s = -1e30f;
        if (k < NTOK) {
            const float4* kp = (const float4*)(Kg + (bh + k) * HD);
            float a = 0.f;
#pragma unroll
            for (int c = 0; c < 16; c++) {
                float4 kv = kp[c];
                float4 qv = ((const float4*)qs)[c];
                a += qv.x * kv.x + qv.y * kv.y + qv.z * kv.z + qv.w * kv.w;
            }
            s = a * 0.125f;
        }
        sc[i] = s;
        lmax = fmaxf(lmax, s);
    }
#pragma unroll
    for (int o = 16; o; o >>= 1) lmax = fmaxf(lmax, __shfl_xor_sync(0xffffffffu, lmax, o));
    if (lane == 0) red[w] = lmax;
    __syncthreads();
    float bmax = red[0];
#pragma unroll
    for (int i = 1; i < 8; i++) bmax = fmaxf(bmax, red[i]);
    __syncthreads();

    float lsum = 0.f;
#pragma unroll
    for (int i = 0; i < 5; i++) {
        int k = tid + i * 256;
        if (k < NTOK) { float e = __expf(sc[i] - bmax); p[k] = e; lsum += e; }
    }
#pragma unroll
    for (int o = 16; o; o >>= 1) lsum += __shfl_xor_sync(0xffffffffu, lsum, o);
    if (lane == 0) red[w] = lsum;
    __syncthreads();
    float bsum = red[0] + red[1] + red[2] + red[3] + red[4] + red[5] + red[6] + red[7];
    float rinv = __frcp_rn(bsum);

    int d = tid & 63, part = tid >> 6;
    float acc = 0.f;
    for (int k = part; k < NTOK; k += 4)
        acc += p[k] * Vg[(bh + k) * HD + d];
    pv[part][d] = acc;
    __syncthreads();
    if (tid < HD) {
        float r = (pv[0][tid] + pv[1][tid] + pv[2][tid] + pv[3][tid]) * rinv;
        O[((size_t)(b * NTOK + q)) * DIM + h * HD + tid] = r;
    }
}

// ---------------------------------------------------------------
extern "C" void kernel_launch(void* const* d_in, const int* in_sizes, int n_in,
                              void* d_out, int out_size)
{
    const float* hidden = (const float*)d_in[0];
    const float* fcos   = (const float*)d_in[1];
    const float* fsin   = (const float*)d_in[2];
    const float* qkv_w  = (const float*)d_in[3];
    const float* out_w  = (const float*)d_in[4];
    const float* wq     = (const float*)d_in[5];
    const float* wk     = (const float*)d_in[6];
    float* out = (float*)d_out;

    float *qkvb, *qb, *kb, *vb, *ab;
    cudaGetSymbolAddress((void**)&qkvb, g_qkv);
    cudaGetSymbolAddress((void**)&qb,   g_q);
    cudaGetSymbolAddress((void**)&kb,   g_k);
    cudaGetSymbolAddress((void**)&vb,   g_v);
    cudaGetSymbolAddress((void**)&ab,   g_attn);

    const int M = B_ * NTOK;                               // 8256
    const int GEMM_SMEM = 4 * 128 * PADK * 2;              // 73,728 B

    cudaFuncSetAttribute(gemm_hmma, cudaFuncAttributeMaxDynamicSharedMemorySize, GEMM_SMEM);

    // 1) QKV projection (HMMA bf16x3): [8256,1024] @ [3072,1024]^T
    dim3 g1(3 * DIM / 128, (M + 127) / 128);
    gemm_hmma<<<g1, 256, GEMM_SMEM>>>(hidden, qkv_w, qkvb, M, 3 * DIM, DIM);

    // 2) RMSNorm + RoPE epilogue -> Q,K,V [B,H,N,64]
    qkv_epilogue<<<(B_ * NTOK * HEADS) / 8, 256>>>(qkvb, fcos, fsin, wq, wk, qb, kb, vb);

    // 3) sparse window attention (patch queries)
    size_t smem = (size_t)(240 * 68 * 2 + 32 * 68 + 32 * 240) * sizeof(float);
    cudaFuncSetAttribute(attn_patch, cudaFuncAttributeMaxDynamicSharedMemorySize, (int)smem);
    attn_patch<<<dim3(GRIDSZ, HEADS, B_), 512, smem>>>(qb, kb, vb, ab);

    // 4) global attention for the 8 special queries
    attn_special<<<dim3(SPECIAL, HEADS, B_), 256>>>(qb, kb, vb, ab);

    // 5) output projection (HMMA bf16x3): [8256,1024] @ [1024,1024]^T
    dim3 g2(DIM / 128, (M + 127) / 128);
    gemm_hmma<<<g2, 256, GEMM_SMEM>>>(ab, out_w, out, M, DIM, DIM);
}